// round 11
// baseline (speedup 1.0000x reference)
#include <cuda_runtime.h>
#include <cstdint>
#include <cfloat>
#include <math_constants.h>

#define FULLMASK 0xFFFFFFFFu

static constexpr int N_ROWS = 262144;
static constexpr int D      = 256;
static constexpr int KCODES = 640;

static constexpr int BM = 64;            // rows per CTA tile
static constexpr int BK = 32;            // k per chunk (floats)
static constexpr int NCH = D / BK;       // 8 chunks
static constexpr int ASU = 18;           // smem row stride in u32 (16 pairs + 2 pad)
static constexpr int P3_BASE  = 385;
static constexpr int P3_CODES = 127;     // col 127 = dup pad, masked via cs=INF

#define MARGIN_RARE 1e-2f
#define MARGIN_BF16 0.75f

__constant__ int c_starts[6] = {0, 129, 257, 385, 513, 577};
__constant__ int c_ends[6]   = {128, 256, 384, 512, 576, 640};

__device__ double g_loss_sum;
__device__ int    g_rare_cnt;
__device__ int    g_rare_idx[N_ROWS];
__device__ float  g_csum[KCODES];        // 0.5 * ||w_k||^2

// x is int32 on device (JAX x64-disabled downcasts the reference's int64).
__device__ __forceinline__ int partition_id(int at) {
    if (at == 5)   return 0;
    if (at == 6)   return 1;
    if (at == 7)   return 2;
    if (at == 119) return 4;
    if (at == 120) return 5;
    return 3;
}

// pack two f32 into bf16x2: lo = a (even k), hi = b (odd k)
__device__ __forceinline__ uint32_t bf16x2(float a, float b) {
    uint32_t r;
    asm("cvt.rn.bf16x2.f32 %0, %1, %2;" : "=r"(r) : "f"(b), "f"(a));
    return r;
}

#define MMA_BF16(d, a, b) \
    asm volatile("mma.sync.aligned.m16n8k16.row.col.f32.bf16.bf16.f32 " \
        "{%0,%1,%2,%3}, {%4,%5,%6,%7}, {%8,%9}, {%0,%1,%2,%3};" \
        : "+f"(d[0]), "+f"(d[1]), "+f"(d[2]), "+f"(d[3]) \
        : "r"(a[0]), "r"(a[1]), "r"(a[2]), "r"(a[3]), "r"(b[0]), "r"(b[1]))

// ---------------------------------------------------------------------------
// smem layout (bytes) — static, < 48KB
static constexpr int SM_CS     = 0;                 // 128 f32
static constexpr int SM_SPID   = 512;               // 64 int
static constexpr int SM_CHOSEN = 768;               // 64 int
static constexpr int SM_WL     = 1024;              // 64 int
static constexpr int SM_SV1    = 1280;              // 64 f32
static constexpr int SM_WSUM   = 1536;              // 8 double
static constexpr int SM_WLCNT  = 1600;              // 1 int
static constexpr int SM_PT     = 1664;              // pv1/pn1/pv2/pn2: 4 * 256 * 4B
static constexpr int SM_BUF    = SM_PT + 4096;      // 5760, 16B aligned
// Single bf16 stage: (64 A-rows + 128 B-rows) * ASU u32 = 192*18*4 = 13824 B
static constexpr int STAGE_U32 = (BM + 128) * ASU;
static constexpr int SCORE_ST  = 131;               // scores stride (floats)
static constexpr int SCORES_BYTES = BM * SCORE_ST * 4;    // 33536 (> stage)
static constexpr int SMEM_MAIN = SM_BUF + SCORES_BYTES;   // 39296

// ---------------------------------------------------------------------------
__global__ void vq_init() {
    g_loss_sum = 0.0;
    g_rare_cnt = 0;
}

// merged csum (blocks < KCODES) + compact (all blocks). <<<1024, 256>>>
__global__ void vq_prep(const float* __restrict__ w, const int* __restrict__ x) {
    __shared__ float ws[8];
    int i = blockIdx.x * 256 + threadIdx.x;
    int at = x[2 * (size_t)i];
    if (partition_id(at) != 3) {
        int p = atomicAdd(&g_rare_cnt, 1);
        g_rare_idx[p] = i;
    }
    if (blockIdx.x < KCODES) {
        int c = blockIdx.x;
        float v = w[(size_t)c * D + threadIdx.x];
        float s = v * v;
        #pragma unroll
        for (int o = 16; o > 0; o >>= 1) s += __shfl_xor_sync(FULLMASK, s, o);
        if ((threadIdx.x & 31) == 0) ws[threadIdx.x >> 5] = s;
        __syncthreads();
        if (threadIdx.x == 0) {
            float t = 0.f;
            #pragma unroll
            for (int k = 0; k < 8; k++) t += ws[k];
            g_csum[c] = 0.5f * t;
        }
    }
}

// top-2 merge with index tiebreak
__device__ __forceinline__ void top2_merge(float& v1, int& n1, float& v2, int& n2,
                                           float vo, int no) {
    if (vo < v1 || (vo == v1 && no < n1)) {
        v2 = v1; n2 = n1; v1 = vo; n1 = no;
    } else if (vo < v2 || (vo == v2 && no < n2)) {
        v2 = vo; n2 = no;
    }
}

// ---------------------------------------------------------------------------
// Main: bf16 mma.sync m16n8k16 GEMM-argmin of all rows vs partition-3 codes.
// Tile 64x128x32, 8 warps (2 row-warps x 4 col-warps), single bf16 stage,
// LDG register prefetch of next chunk issued before compute.
// ---------------------------------------------------------------------------
__global__ void __launch_bounds__(256) vq_main_mma(
    const int* __restrict__ x, const float* __restrict__ e,
    const float* __restrict__ w, float* __restrict__ out)
{
    __shared__ __align__(16) char sm[SMEM_MAIN];
    float*  cs      = (float*)(sm + SM_CS);
    int*    spid    = (int*)(sm + SM_SPID);
    int*    schosen = (int*)(sm + SM_CHOSEN);
    int*    wl      = (int*)(sm + SM_WL);
    float*  sv1     = (float*)(sm + SM_SV1);
    double* wsum    = (double*)(sm + SM_WSUM);
    int*    wlcnt   = (int*)(sm + SM_WLCNT);
    float*  pv1     = (float*)(sm + SM_PT);
    int*    pn1     = (int*)(sm + SM_PT + 1024);
    float*  pv2     = (float*)(sm + SM_PT + 2048);
    int*    pn2     = (int*)(sm + SM_PT + 3072);
    uint32_t* S     = (uint32_t*)(sm + SM_BUF);     // bf16 stage (u32 pairs)
    float*  scores  = (float*)(sm + SM_BUF);        // overlay after mainloop

    const int tid  = threadIdx.x;
    const int wid  = tid >> 5;
    const int lane = tid & 31;
    const int g    = lane >> 2;
    const int tig  = lane & 3;
    const int wrow = wid & 1;         // 2 row-warps (32 rows each)
    const int wcol = wid >> 1;        // 4 col-warps (32 cols each)
    const int rbase = blockIdx.x * BM;

    if (tid == 0) *wlcnt = 0;
    if (tid < 128)
        cs[tid] = (tid < P3_CODES) ? g_csum[P3_BASE + tid] : CUDART_INF_F;
    if (tid < BM)
        spid[tid] = partition_id(x[2 * (size_t)(rbase + tid)]);

    // loader geometry: id -> (row, seg); A ids 0..511, B ids 0..1023
    const int arow0 = tid >> 3, aseg = tid & 7;     // +t*256 -> row += 32
    // LDG next chunk's fp32 into regs
    float4 r[6];
    auto ldg_chunk = [&](int kc) {
        #pragma unroll
        for (int t = 0; t < 2; t++) {
            int row = arow0 + t * 32;
            r[t] = *(const float4*)(e + (size_t)(rbase + row) * D + kc * BK + aseg * 4);
        }
        #pragma unroll
        for (int t = 0; t < 4; t++) {
            int row = arow0 + t * 32;
            int wr_ = row < P3_CODES ? row : P3_CODES - 1;
            r[2 + t] = *(const float4*)(w + (size_t)(P3_BASE + wr_) * D + kc * BK + aseg * 4);
        }
    };
    // cvt + store current regs to the stage
    auto sts_chunk = [&]() {
        #pragma unroll
        for (int t = 0; t < 2; t++) {
            int row = arow0 + t * 32;
            uint32_t lo = bf16x2(r[t].x, r[t].y);
            uint32_t hi = bf16x2(r[t].z, r[t].w);
            *(uint2*)&S[row * ASU + aseg * 2] = make_uint2(lo, hi);
        }
        #pragma unroll
        for (int t = 0; t < 4; t++) {
            int row = arow0 + t * 32;
            uint32_t lo = bf16x2(r[2 + t].x, r[2 + t].y);
            uint32_t hi = bf16x2(r[2 + t].z, r[2 + t].w);
            *(uint2*)&S[(BM + row) * ASU + aseg * 2] = make_uint2(lo, hi);
        }
    };

    float acc[2][4][4];
    #pragma unroll
    for (int rT = 0; rT < 2; rT++)
        #pragma unroll
        for (int c = 0; c < 4; c++)
            #pragma unroll
            for (int v = 0; v < 4; v++) acc[rT][c][v] = 0.f;

    const int aR = (wrow * 32 + g) * ASU;           // A frag base (rT=0, row g)
    const int bR = (BM + wcol * 32 + g) * ASU;      // B frag base (c=0, row g)

    ldg_chunk(0);
    for (int kc = 0; kc < NCH; kc++) {
        __syncthreads();                 // stage free (prev chunk consumed)
        sts_chunk();
        __syncthreads();                 // stage ready
        if (kc + 1 < NCH) ldg_chunk(kc + 1);

        #pragma unroll
        for (int ks = 0; ks < 2; ks++) {
            const int p0 = ks * 8 + tig;         // pair index (k = 2*p)
            uint32_t a[2][4];
            #pragma unroll
            for (int rT = 0; rT < 2; rT++) {
                int rb = aR + rT * 16 * ASU;
                a[rT][0] = S[rb + p0];               // row g,   k 2tig..
                a[rT][1] = S[rb + 8 * ASU + p0];     // row g+8
                a[rT][2] = S[rb + p0 + 4];           // row g,   k 2tig+8..
                a[rT][3] = S[rb + 8 * ASU + p0 + 4]; // row g+8
            }
            #pragma unroll
            for (int c = 0; c < 4; c++) {
                uint32_t b[2];
                int nb = bR + c * 8 * ASU;
                b[0] = S[nb + p0];
                b[1] = S[nb + p0 + 4];
                MMA_BF16(acc[0][c], a[0], b);
                MMA_BF16(acc[1][c], a[1], b);
            }
        }
    }
    __syncthreads();   // all warps done reading stage before scores overlay

    // ---- scores -> smem overlay; per-thread top-2, in-warp tig reduce ----
    #pragma unroll
    for (int rT = 0; rT < 2; rT++) {
        #pragma unroll
        for (int hv = 0; hv < 2; hv++) {
            const int row = wrow * 32 + rT * 16 + hv * 8 + g;
            float v1 = CUDART_INF_F, v2 = CUDART_INF_F;
            int n1 = 0x7FFFFFFF, n2 = 0x7FFFFFFF;
            #pragma unroll
            for (int c = 0; c < 4; c++) {
                #pragma unroll
                for (int p = 0; p < 2; p++) {
                    const int col = wcol * 32 + c * 8 + 2 * tig + p;
                    float sc = cs[col] - acc[rT][c][hv * 2 + p];
                    scores[row * SCORE_ST + col] = sc;
                    top2_merge(v1, n1, v2, n2, sc, col);
                }
            }
            #pragma unroll
            for (int o = 1; o <= 2; o <<= 1) {
                float ov1 = __shfl_xor_sync(FULLMASK, v1, o);
                int   on1 = __shfl_xor_sync(FULLMASK, n1, o);
                float ov2 = __shfl_xor_sync(FULLMASK, v2, o);
                int   on2 = __shfl_xor_sync(FULLMASK, n2, o);
                top2_merge(v1, n1, v2, n2, ov1, on1);
                top2_merge(v1, n1, v2, n2, ov2, on2);
            }
            if (tig == 0) {
                pv1[row * 4 + wcol] = v1;  pn1[row * 4 + wcol] = n1;
                pv2[row * 4 + wcol] = v2;  pn2[row * 4 + wcol] = n2;
            }
        }
    }
    __syncthreads();

    // ---- per-row reduce over 4 col-warp slots ----
    if (tid < BM) {
        float v1 = CUDART_INF_F, v2 = CUDART_INF_F;
        int n1 = 0x7FFFFFFF, n2 = 0x7FFFFFFF;
        #pragma unroll
        for (int s = 0; s < 4; s++) {
            top2_merge(v1, n1, v2, n2, pv1[tid * 4 + s], pn1[tid * 4 + s]);
            top2_merge(v1, n1, v2, n2, pv2[tid * 4 + s], pn2[tid * 4 + s]);
        }
        schosen[tid] = P3_BASE + n1;
        sv1[tid] = v1;
        if (v2 - v1 < MARGIN_BF16) {
            int p = atomicAdd(wlcnt, 1);
            wl[p] = tid;
        }
    }
    __syncthreads();

    // ---- exact fp64 rescore of flagged rows (warp per row) ----
    {
        const int nwl = *wlcnt;
        for (int k = wid; k < nwl; k += 8) {
            const int row = wl[k];
            const float thr = sv1[row] + MARGIN_BF16;
            const float* er = e + (size_t)(rbase + row) * D;
            float ev[8];
            #pragma unroll
            for (int j = 0; j < 8; j++) ev[j] = er[lane + 32 * j];
            double bestd = DBL_MAX;
            int    bestc = 0x7FFFFFFF;
            #pragma unroll
            for (int base = 0; base < 128; base += 32) {
                int c = base + lane;
                bool ok = (c < P3_CODES) && (scores[row * SCORE_ST + c] < thr);
                unsigned m = __ballot_sync(FULLMASK, ok);
                while (m) {
                    int c2 = base + __ffs(m) - 1;
                    m &= m - 1;
                    const float* wr = w + (size_t)(P3_BASE + c2) * D;
                    double s = 0.0;
                    #pragma unroll
                    for (int j = 0; j < 8; j++) {
                        double t = (double)ev[j] - (double)wr[lane + 32 * j];
                        s += t * t;
                    }
                    #pragma unroll
                    for (int o = 16; o > 0; o >>= 1)
                        s += __shfl_xor_sync(FULLMASK, s, o);
                    if (s < bestd) { bestd = s; bestc = c2; }   // ascending c2
                }
            }
            if (lane == 0) schosen[row] = P3_BASE + bestc;
        }
    }
    __syncthreads();

    // ---- output + loss for pid3 rows (warp per 8 rows) ----
    double ls = 0.0;
    #pragma unroll
    for (int j = 0; j < 8; j++) {
        const int row = wid * 8 + j;
        if (spid[row] != 3) continue;
        const float* er = e + (size_t)(rbase + row) * D;
        const float* wr = w + (size_t)schosen[row] * D;
        float* orow = out + (size_t)(rbase + row) * D;
        #pragma unroll
        for (int it = 0; it < 2; it++) {
            int f4 = it * 32 + lane;
            float4 ev = *(const float4*)(er + f4 * 4);
            float4 qv = *(const float4*)(wr + f4 * 4);
            float dx = qv.x - ev.x, dy = qv.y - ev.y;
            float dz = qv.z - ev.z, dw = qv.w - ev.w;
            float4 ov;
            ov.x = ev.x + dx; ov.y = ev.y + dy; ov.z = ev.z + dz; ov.w = ev.w + dw;
            *(float4*)(orow + f4 * 4) = ov;
            ls += (double)dx * dx + (double)dy * dy +
                  (double)dz * dz + (double)dw * dw;
        }
    }
    #pragma unroll
    for (int o = 16; o > 0; o >>= 1) ls += __shfl_down_sync(FULLMASK, ls, o);
    if (lane == 0) wsum[wid] = ls;
    __syncthreads();
    if (tid == 0) {
        double s = 0.0;
        #pragma unroll
        for (int i = 0; i < 8; i++) s += wsum[i];
        atomicAdd(&g_loss_sum, s);
    }
}

// ---------------------------------------------------------------------------
// Rare rows: grid-stride, one warp per compacted row. Coalesced w reads,
// 4 codes in flight for ILP.
__global__ void __launch_bounds__(1024) vq_rare(
    const int* __restrict__ x, const float* __restrict__ e,
    const float* __restrict__ w, float* __restrict__ out)
{
    __shared__ double wsums[32];
    const int lane = threadIdx.x & 31;
    const int wloc = threadIdx.x >> 5;
    const int cnt  = g_rare_cnt;

    double ls = 0.0;
    for (int wg = blockIdx.x * 32 + wloc; wg < cnt; wg += gridDim.x * 32) {
        const int row = g_rare_idx[wg];
        const int pid = partition_id(x[2 * (size_t)row]);
        const int s   = c_starts[pid];
        const int en  = c_ends[pid];
        float ev[8];
        #pragma unroll
        for (int j = 0; j < 8; j++) ev[j] = e[(size_t)row * D + lane + 32 * j];

        float v1 = CUDART_INF_F, v2 = CUDART_INF_F;
        int   i1 = s, i2 = s;
        for (int c = s; c < en; c += 4) {
            const float* wr[4];
            float d[4];
            #pragma unroll
            for (int q = 0; q < 4; q++) {
                int cq = c + q < en ? c + q : en - 1;
                wr[q] = w + (size_t)cq * D;
                d[q] = 0.f;
            }
            #pragma unroll
            for (int j = 0; j < 8; j++) {
                const int col = lane + 32 * j;
                float evj = ev[j];
                d[0] = fmaf(evj, wr[0][col], d[0]);
                d[1] = fmaf(evj, wr[1][col], d[1]);
                d[2] = fmaf(evj, wr[2][col], d[2]);
                d[3] = fmaf(evj, wr[3][col], d[3]);
            }
            #pragma unroll
            for (int o = 16; o > 0; o >>= 1) {
                d[0] += __shfl_xor_sync(FULLMASK, d[0], o);
                d[1] += __shfl_xor_sync(FULLMASK, d[1], o);
                d[2] += __shfl_xor_sync(FULLMASK, d[2], o);
                d[3] += __shfl_xor_sync(FULLMASK, d[3], o);
            }
            #pragma unroll
            for (int q = 0; q < 4; q++) {
                if (c + q < en)
                    top2_merge(v1, i1, v2, i2, g_csum[c + q] - d[q], c + q);
            }
        }
        int best = i1;
        if (v2 - v1 < MARGIN_RARE) {
            const float* wa = w + (size_t)i1 * D;
            const float* wb = w + (size_t)i2 * D;
            double da = 0.0, db = 0.0;
            #pragma unroll
            for (int j = 0; j < 8; j++) {
                int col = lane + 32 * j;
                double t;
                t = (double)ev[j] - wa[col]; da += t * t;
                t = (double)ev[j] - wb[col]; db += t * t;
            }
            #pragma unroll
            for (int o = 16; o > 0; o >>= 1) {
                da += __shfl_xor_sync(FULLMASK, da, o);
                db += __shfl_xor_sync(FULLMASK, db, o);
            }
            if (db < da || (db == da && i2 < i1)) best = i2;
        }
        const float* wq = w + (size_t)best * D;
        #pragma unroll
        for (int j = 0; j < 8; j++) {
            int col = lane + 32 * j;
            float ee = ev[j];
            float df = wq[col] - ee;
            out[(size_t)row * D + col] = ee + df;
            ls += (double)df * df;
        }
    }
    #pragma unroll
    for (int o = 16; o > 0; o >>= 1) ls += __shfl_down_sync(FULLMASK, ls, o);
    if (lane == 0) wsums[wloc] = ls;
    __syncthreads();
    if (threadIdx.x == 0) {
        double s = 0.0;
        #pragma unroll
        for (int i = 0; i < 32; i++) s += wsums[i];
        if (s != 0.0) atomicAdd(&g_loss_sum, s);
    }
}

// ---------------------------------------------------------------------------
__global__ void vq_finalize(float* out, long long n_out) {
    double mean = g_loss_sum / (double)((long long)N_ROWS * D);
    float cl = (float)mean;
    out[n_out - 3] = cl;               // codebook_loss
    out[n_out - 2] = cl;               // gnn_loss (identical value)
    out[n_out - 1] = cl + 0.25f * cl;  // vq_loss
}

// ---------------------------------------------------------------------------
extern "C" void kernel_launch(void* const* d_in, const int* in_sizes, int n_in,
                              void* d_out, int out_size) {
    const int*   x = (const int*)d_in[0];
    const float* e = (const float*)d_in[1];
    const float* w = (const float*)d_in[2];
    float* out = (float*)d_out;

    vq_init<<<1, 1>>>();
    vq_prep<<<N_ROWS / 256, 256>>>(w, x);
    vq_main_mma<<<N_ROWS / BM, 256>>>(x, e, w, out);
    vq_rare<<<256, 1024>>>(x, e, w, out);
    vq_finalize<<<1, 1>>>(out, (long long)out_size);
}

// round 14
// speedup vs baseline: 1.3133x; 1.3133x over previous
#include <cuda_runtime.h>
#include <cstdint>
#include <cfloat>
#include <math_constants.h>

#define FULLMASK 0xFFFFFFFFu

static constexpr int N_ROWS = 262144;
static constexpr int D      = 256;
static constexpr int KCODES = 640;

static constexpr int BM = 64;            // rows per CTA tile
static constexpr int BK = 16;            // k-chunk (floats)
static constexpr int P3_BASE  = 385;
static constexpr int P3_CODES = 127;     // col 127 = dup pad, masked via cs=INF

#define MARGIN_RARE 1e-2f
#define MARGIN_TF32 0.5f

__constant__ int c_starts[6] = {0, 129, 257, 385, 513, 577};
__constant__ int c_ends[6]   = {128, 256, 384, 512, 576, 640};

__device__ double g_loss_sum;
__device__ int    g_rare_cnt;
__device__ int    g_rare_idx[N_ROWS];
__device__ float  g_csum[KCODES];        // 0.5 * ||w_k||^2

// x is int32 on device (JAX x64-disabled downcasts the reference's int64).
__device__ __forceinline__ int partition_id(int at) {
    if (at == 5)   return 0;
    if (at == 6)   return 1;
    if (at == 7)   return 2;
    if (at == 119) return 4;
    if (at == 120) return 5;
    return 3;
}

__device__ __forceinline__ uint32_t smem_u32(const void* p) {
    uint32_t a;
    asm("{ .reg .u64 t; cvta.to.shared.u64 t, %1; cvt.u32.u64 %0, t; }"
        : "=r"(a) : "l"(p));
    return a;
}

__device__ __forceinline__ void cp16(uint32_t dst, const void* src) {
    asm volatile("cp.async.cg.shared.global [%0], [%1], 16;"
                 :: "r"(dst), "l"(src) : "memory");
}
#define CP_COMMIT() asm volatile("cp.async.commit_group;" ::: "memory")
#define CP_WAIT(n)  asm volatile("cp.async.wait_group %0;" :: "n"(n) : "memory")

#define MMA_TF32(d, a, b0, b1) \
    asm volatile("mma.sync.aligned.m16n8k8.row.col.f32.tf32.tf32.f32 " \
        "{%0,%1,%2,%3}, {%4,%5,%6,%7}, {%8,%9}, {%0,%1,%2,%3};" \
        : "+f"(d[0]), "+f"(d[1]), "+f"(d[2]), "+f"(d[3]) \
        : "r"(a[0]), "r"(a[1]), "r"(a[2]), "r"(a[3]), "r"(b0), "r"(b1))

// ---------------------------------------------------------------------------
// smem layout (bytes) — static, < 48KB
static constexpr int SM_CS     = 0;                 // 128 f32
static constexpr int SM_SPID   = 512;               // 64 int
static constexpr int SM_CHOSEN = 768;               // 64 int
static constexpr int SM_WL     = 1024;              // 64 int
static constexpr int SM_SV1    = 1280;              // 64 f32
static constexpr int SM_WSUM   = 1536;              // 8 double
static constexpr int SM_WLCNT  = 1600;              // 1 int
static constexpr int SM_PT     = 1664;              // pv1/pn1/pv2/pn2: 4 * 256 * 4B
static constexpr int SM_BUF    = SM_PT + 4096;      // 5760, 16B aligned
// Stage: A 64 rows x 16 f + B 128 rows x 16 f = 3072 floats = 12288 B (XOR swizzled)
static constexpr int STAGE_BYTES = (BM + 128) * BK * 4;   // 12288
static constexpr int N_STAGE = 3;
static constexpr int SCORE_ST  = 131;               // scores stride (floats)
static constexpr int SMEM_MAIN = SM_BUF + N_STAGE * STAGE_BYTES;  // 42624

// ---------------------------------------------------------------------------
__global__ void vq_init() {
    g_loss_sum = 0.0;
    g_rare_cnt = 0;
}

// merged csum (blocks < KCODES) + compact (all blocks). <<<1024, 256>>>
__global__ void vq_prep(const float* __restrict__ w, const int* __restrict__ x) {
    __shared__ float ws[8];
    int i = blockIdx.x * 256 + threadIdx.x;
    int at = x[2 * (size_t)i];
    if (partition_id(at) != 3) {
        int p = atomicAdd(&g_rare_cnt, 1);
        g_rare_idx[p] = i;
    }
    if (blockIdx.x < KCODES) {
        int c = blockIdx.x;
        float v = w[(size_t)c * D + threadIdx.x];
        float s = v * v;
        #pragma unroll
        for (int o = 16; o > 0; o >>= 1) s += __shfl_xor_sync(FULLMASK, s, o);
        if ((threadIdx.x & 31) == 0) ws[threadIdx.x >> 5] = s;
        __syncthreads();
        if (threadIdx.x == 0) {
            float t = 0.f;
            #pragma unroll
            for (int k = 0; k < 8; k++) t += ws[k];
            g_csum[c] = 0.5f * t;
        }
    }
}

// top-2 merge with index tiebreak
__device__ __forceinline__ void top2_merge(float& v1, int& n1, float& v2, int& n2,
                                           float vo, int no) {
    if (vo < v1 || (vo == v1 && no < n1)) {
        v2 = v1; n2 = n1; v1 = vo; n1 = no;
    } else if (vo < v2 || (vo == v2 && no < n2)) {
        v2 = vo; n2 = no;
    }
}

// ---------------------------------------------------------------------------
// Main: tf32 mma.sync GEMM-argmin of all rows vs partition-3 codes.
// Tile 64x128x16, 8 warps (2 row-warps x 4 col-warps), 3-stage cp.async,
// one barrier per k-chunk, XOR bank swizzle. (R10-proven, ~420us)
// ---------------------------------------------------------------------------
__global__ void __launch_bounds__(256) vq_main_mma(
    const int* __restrict__ x, const float* __restrict__ e,
    const float* __restrict__ w, float* __restrict__ out)
{
    __shared__ __align__(16) char sm[SMEM_MAIN];
    const uint32_t smb = smem_u32(sm);
    float*  cs      = (float*)(sm + SM_CS);
    int*    spid    = (int*)(sm + SM_SPID);
    int*    schosen = (int*)(sm + SM_CHOSEN);
    int*    wl      = (int*)(sm + SM_WL);
    float*  sv1     = (float*)(sm + SM_SV1);
    double* wsum    = (double*)(sm + SM_WSUM);
    int*    wlcnt   = (int*)(sm + SM_WLCNT);
    float*  pv1     = (float*)(sm + SM_PT);
    int*    pn1     = (int*)(sm + SM_PT + 1024);
    float*  pv2     = (float*)(sm + SM_PT + 2048);
    int*    pn2     = (int*)(sm + SM_PT + 3072);
    float*  scores  = (float*)(sm + SM_BUF);        // overlay after mainloop

    const int tid  = threadIdx.x;
    const int wid  = tid >> 5;
    const int lane = tid & 31;
    const int g    = lane >> 2;
    const int tig  = lane & 3;
    const int wrow = wid & 1;         // 2 row-warps (32 rows each)
    const int wcol = wid >> 1;        // 4 col-warps (32 cols each)
    const int rbase = blockIdx.x * BM;

    if (tid == 0) *wlcnt = 0;
    if (tid < 128)
        cs[tid] = (tid < P3_CODES) ? g_csum[P3_BASE + tid] : CUDART_INF_F;
    if (tid < BM)
        spid[tid] = partition_id(x[2 * (size_t)(rbase + tid)]);

    // ---- stage issue (A: 64 e-rows, B: 128 w-codes, 16 k each, swizzled) ----
    auto issue = [&](int buf, int kc) {
        uint32_t base = smb + SM_BUF + buf * STAGE_BYTES;
        {   // A: 64 rows * 4 segs = 256 cp16
            int row = tid >> 2, seg = tid & 3;
            int s2 = seg ^ (row & 3);
            cp16(base + (row * 16 + s2 * 4) * 4,
                 e + (size_t)(rbase + row) * D + kc * BK + seg * 4);
        }
        #pragma unroll
        for (int t = 0; t < 2; t++) {   // B: 128 rows * 4 segs = 512 cp16
            int id = tid + t * 256;
            int row = id >> 2, seg = id & 3;
            int wr = row < P3_CODES ? row : P3_CODES - 1;
            int s2 = seg ^ (row & 3);
            cp16(base + 4096 + (row * 16 + s2 * 4) * 4,
                 w + (size_t)(P3_BASE + wr) * D + kc * BK + seg * 4);
        }
    };

    float acc[2][4][4];
    #pragma unroll
    for (int rT = 0; rT < 2; rT++)
        #pragma unroll
        for (int c = 0; c < 4; c++)
            #pragma unroll
            for (int v = 0; v < 4; v++) acc[rT][c][v] = 0.f;

    // swizzled frag columns: phys col = col ^ ((row&3)<<2); all frag rows
    // differ by multiples of 8, so (row&3) == (g&3) for every frag row.
    const int ct = tig ^ ((g & 3) << 2);
    const int arow0 = (wrow * 32 + g) * 16;   // float index of A row (rT=0)
    const int brow0 = (wcol * 32 + g) * 16;   // float index of B row (c=0)

    issue(0, 0); CP_COMMIT();
    issue(1, 1); CP_COMMIT();

    for (int kc = 0; kc < 16; kc++) {
        if (kc < 15) { CP_WAIT(1); } else { CP_WAIT(0); }
        __syncthreads();
        if (kc + 2 < 16) { issue((kc + 2) % N_STAGE, kc + 2); CP_COMMIT(); }

        const uint32_t* Abuf =
            (const uint32_t*)(sm + SM_BUF + (kc % N_STAGE) * STAGE_BYTES);
        const uint32_t* Bbuf = Abuf + BM * 16;   // +1024 floats

        #pragma unroll
        for (int ks = 0; ks < 2; ks++) {
            const int c0 = ct ^ (ks * 8);
            const int c4 = c0 ^ 4;
            uint32_t a[2][4];
            #pragma unroll
            for (int rT = 0; rT < 2; rT++) {
                int rb = arow0 + rT * 256;       // +16 rows
                a[rT][0] = Abuf[rb + c0];
                a[rT][1] = Abuf[rb + 128 + c0];  // +8 rows
                a[rT][2] = Abuf[rb + c4];
                a[rT][3] = Abuf[rb + 128 + c4];
            }
            #pragma unroll
            for (int c = 0; c < 4; c++) {
                int nb = brow0 + c * 128;        // +8 rows per c
                uint32_t b0 = Bbuf[nb + c0], b1 = Bbuf[nb + c4];
                MMA_TF32(acc[0][c], a[0], b0, b1);
                MMA_TF32(acc[1][c], a[1], b0, b1);
            }
        }
    }
    __syncthreads();   // all warps done reading stages before scores overlay

    // ---- scores -> smem overlay; per-thread top-2, in-warp tig reduce ----
    #pragma unroll
    for (int rT = 0; rT < 2; rT++) {
        #pragma unroll
        for (int hv = 0; hv < 2; hv++) {
            const int row = wrow * 32 + rT * 16 + hv * 8 + g;
            float v1 = CUDART_INF_F, v2 = CUDART_INF_F;
            int n1 = 0x7FFFFFFF, n2 = 0x7FFFFFFF;
            #pragma unroll
            for (int c = 0; c < 4; c++) {
                #pragma unroll
                for (int p = 0; p < 2; p++) {
                    const int col = wcol * 32 + c * 8 + 2 * tig + p;
                    float sc = cs[col] - acc[rT][c][hv * 2 + p];
                    scores[row * SCORE_ST + col] = sc;
                    top2_merge(v1, n1, v2, n2, sc, col);
                }
            }
            #pragma unroll
            for (int o = 1; o <= 2; o <<= 1) {
                float ov1 = __shfl_xor_sync(FULLMASK, v1, o);
                int   on1 = __shfl_xor_sync(FULLMASK, n1, o);
                float ov2 = __shfl_xor_sync(FULLMASK, v2, o);
                int   on2 = __shfl_xor_sync(FULLMASK, n2, o);
                top2_merge(v1, n1, v2, n2, ov1, on1);
                top2_merge(v1, n1, v2, n2, ov2, on2);
            }
            if (tig == 0) {
                pv1[row * 4 + wcol] = v1;  pn1[row * 4 + wcol] = n1;
                pv2[row * 4 + wcol] = v2;  pn2[row * 4 + wcol] = n2;
            }
        }
    }
    __syncthreads();

    // ---- per-row reduce over 4 col-warp slots ----
    if (tid < BM) {
        float v1 = CUDART_INF_F, v2 = CUDART_INF_F;
        int n1 = 0x7FFFFFFF, n2 = 0x7FFFFFFF;
        #pragma unroll
        for (int s = 0; s < 4; s++) {
            top2_merge(v1, n1, v2, n2, pv1[tid * 4 + s], pn1[tid * 4 + s]);
            top2_merge(v1, n1, v2, n2, pv2[tid * 4 + s], pn2[tid * 4 + s]);
        }
        schosen[tid] = P3_BASE + n1;
        sv1[tid] = v1;
        if (v2 - v1 < MARGIN_TF32) {
            int p = atomicAdd(wlcnt, 1);
            wl[p] = tid;
        }
    }
    __syncthreads();

    // ---- exact fp64 rescore of flagged rows (warp per row) ----
    {
        const int nwl = *wlcnt;
        for (int k = wid; k < nwl; k += 8) {
            const int row = wl[k];
            const float thr = sv1[row] + MARGIN_TF32;
            const float* er = e + (size_t)(rbase + row) * D;
            float ev[8];
            #pragma unroll
            for (int j = 0; j < 8; j++) ev[j] = er[lane + 32 * j];
            double bestd = DBL_MAX;
            int    bestc = 0x7FFFFFFF;
            #pragma unroll
            for (int base = 0; base < 128; base += 32) {
                int c = base + lane;
                bool ok = (c < P3_CODES) && (scores[row * SCORE_ST + c] < thr);
                unsigned m = __ballot_sync(FULLMASK, ok);
                while (m) {
                    int c2 = base + __ffs(m) - 1;
                    m &= m - 1;
                    const float* wr = w + (size_t)(P3_BASE + c2) * D;
                    double s = 0.0;
                    #pragma unroll
                    for (int j = 0; j < 8; j++) {
                        double t = (double)ev[j] - (double)wr[lane + 32 * j];
                        s += t * t;
                    }
                    #pragma unroll
                    for (int o = 16; o > 0; o >>= 1)
                        s += __shfl_xor_sync(FULLMASK, s, o);
                    if (s < bestd) { bestd = s; bestc = c2; }   // ascending c2
                }
            }
            if (lane == 0) schosen[row] = P3_BASE + bestc;
        }
    }
    __syncthreads();

    // ---- output + loss for pid3 rows (warp per 8 rows) ----
    double ls = 0.0;
    #pragma unroll
    for (int j = 0; j < 8; j++) {
        const int row = wid * 8 + j;
        if (spid[row] != 3) continue;
        const float* er = e + (size_t)(rbase + row) * D;
        const float* wr = w + (size_t)schosen[row] * D;
        float* orow = out + (size_t)(rbase + row) * D;
        #pragma unroll
        for (int it = 0; it < 2; it++) {
            int f4 = it * 32 + lane;
            float4 ev = *(const float4*)(er + f4 * 4);
            float4 qv = *(const float4*)(wr + f4 * 4);
            float dx = qv.x - ev.x, dy = qv.y - ev.y;
            float dz = qv.z - ev.z, dw = qv.w - ev.w;
            float4 ov;
            ov.x = ev.x + dx; ov.y = ev.y + dy; ov.z = ev.z + dz; ov.w = ev.w + dw;
            *(float4*)(orow + f4 * 4) = ov;
            ls += (double)dx * dx + (double)dy * dy +
                  (double)dz * dz + (double)dw * dw;
        }
    }
    #pragma unroll
    for (int o = 16; o > 0; o >>= 1) ls += __shfl_down_sync(FULLMASK, ls, o);
    if (lane == 0) wsum[wid] = ls;
    __syncthreads();
    if (tid == 0) {
        double s = 0.0;
        #pragma unroll
        for (int i = 0; i < 8; i++) s += wsum[i];
        atomicAdd(&g_loss_sum, s);
    }
}

// ---------------------------------------------------------------------------
// Rare rows: one warp per compacted row. Lane owns d = 4L..4L+3 (+128):
// LDG.128 per lane (4x fewer LSU issues than scalar), 4 codes in flight.
// Grid 512 blocks = 16K warps: single pass over ~11K rows.
__global__ void __launch_bounds__(1024) vq_rare(
    const int* __restrict__ x, const float* __restrict__ e,
    const float* __restrict__ w, float* __restrict__ out)
{
    __shared__ double wsums[32];
    const int lane = threadIdx.x & 31;
    const int wloc = threadIdx.x >> 5;
    const int cnt  = g_rare_cnt;

    double ls = 0.0;
    for (int wg = blockIdx.x * 32 + wloc; wg < cnt; wg += gridDim.x * 32) {
        const int row = g_rare_idx[wg];
        const int pid = partition_id(x[2 * (size_t)row]);
        const int s   = c_starts[pid];
        const int en  = c_ends[pid];
        const float4* er4 = (const float4*)(e + (size_t)row * D);
        float4 ev4[2];
        ev4[0] = er4[lane];
        ev4[1] = er4[32 + lane];

        float v1 = CUDART_INF_F, v2 = CUDART_INF_F;
        int   i1 = s, i2 = s;
        for (int c = s; c < en; c += 4) {
            const float4* wr[4];
            float d[4];
            #pragma unroll
            for (int q = 0; q < 4; q++) {
                int cq = c + q < en ? c + q : en - 1;
                wr[q] = (const float4*)(w + (size_t)cq * D);
                d[q] = 0.f;
            }
            #pragma unroll
            for (int t = 0; t < 2; t++) {
                const float4 ev = ev4[t];
                #pragma unroll
                for (int q = 0; q < 4; q++) {
                    float4 wv = wr[q][t * 32 + lane];
                    d[q] = fmaf(ev.x, wv.x, d[q]);
                    d[q] = fmaf(ev.y, wv.y, d[q]);
                    d[q] = fmaf(ev.z, wv.z, d[q]);
                    d[q] = fmaf(ev.w, wv.w, d[q]);
                }
            }
            #pragma unroll
            for (int o = 16; o > 0; o >>= 1) {
                d[0] += __shfl_xor_sync(FULLMASK, d[0], o);
                d[1] += __shfl_xor_sync(FULLMASK, d[1], o);
                d[2] += __shfl_xor_sync(FULLMASK, d[2], o);
                d[3] += __shfl_xor_sync(FULLMASK, d[3], o);
            }
            #pragma unroll
            for (int q = 0; q < 4; q++) {
                if (c + q < en)
                    top2_merge(v1, i1, v2, i2, g_csum[c + q] - d[q], c + q);
            }
        }
        int best = i1;
        if (v2 - v1 < MARGIN_RARE) {
            const float4* wa = (const float4*)(w + (size_t)i1 * D);
            const float4* wb = (const float4*)(w + (size_t)i2 * D);
            double da = 0.0, db = 0.0;
            #pragma unroll
            for (int t = 0; t < 2; t++) {
                const float4 ev = ev4[t];
                float4 av = wa[t * 32 + lane];
                float4 bv = wb[t * 32 + lane];
                double u;
                u = (double)ev.x - av.x; da += u * u;
                u = (double)ev.y - av.y; da += u * u;
                u = (double)ev.z - av.z; da += u * u;
                u = (double)ev.w - av.w; da += u * u;
                u = (double)ev.x - bv.x; db += u * u;
                u = (double)ev.y - bv.y; db += u * u;
                u = (double)ev.z - bv.z; db += u * u;
                u = (double)ev.w - bv.w; db += u * u;
            }
            #pragma unroll
            for (int o = 16; o > 0; o >>= 1) {
                da += __shfl_xor_sync(FULLMASK, da, o);
                db += __shfl_xor_sync(FULLMASK, db, o);
            }
            if (db < da || (db == da && i2 < i1)) best = i2;
        }
        const float4* wq = (const float4*)(w + (size_t)best * D);
        float4* orow4 = (float4*)(out + (size_t)row * D);
        #pragma unroll
        for (int t = 0; t < 2; t++) {
            const float4 ev = ev4[t];
            float4 qv = wq[t * 32 + lane];
            float dx = qv.x - ev.x, dy = qv.y - ev.y;
            float dz = qv.z - ev.z, dw = qv.w - ev.w;
            float4 ov;
            ov.x = ev.x + dx; ov.y = ev.y + dy; ov.z = ev.z + dz; ov.w = ev.w + dw;
            orow4[t * 32 + lane] = ov;
            ls += (double)dx * dx + (double)dy * dy +
                  (double)dz * dz + (double)dw * dw;
        }
    }
    #pragma unroll
    for (int o = 16; o > 0; o >>= 1) ls += __shfl_down_sync(FULLMASK, ls, o);
    if (lane == 0) wsums[wloc] = ls;
    __syncthreads();
    if (threadIdx.x == 0) {
        double s = 0.0;
        #pragma unroll
        for (int i = 0; i < 32; i++) s += wsums[i];
        if (s != 0.0) atomicAdd(&g_loss_sum, s);
    }
}

// ---------------------------------------------------------------------------
__global__ void vq_finalize(float* out, long long n_out) {
    double mean = g_loss_sum / (double)((long long)N_ROWS * D);
    float cl = (float)mean;
    out[n_out - 3] = cl;               // codebook_loss
    out[n_out - 2] = cl;               // gnn_loss (identical value)
    out[n_out - 1] = cl + 0.25f * cl;  // vq_loss
}

// ---------------------------------------------------------------------------
extern "C" void kernel_launch(void* const* d_in, const int* in_sizes, int n_in,
                              void* d_out, int out_size) {
    const int*   x = (const int*)d_in[0];
    const float* e = (const float*)d_in[1];
    const float* w = (const float*)d_in[2];
    float* out = (float*)d_out;

    vq_init<<<1, 1>>>();
    vq_prep<<<N_ROWS / 256, 256>>>(w, x);
    vq_main_mma<<<N_ROWS / BM, 256>>>(x, e, w, out);
    vq_rare<<<512, 1024>>>(x, e, w, out);
    vq_finalize<<<1, 1>>>(out, (long long)out_size);
}